// round 17
// baseline (speedup 1.0000x reference)
#include <cuda_runtime.h>
#include <cuda_fp16.h>
#include <cstdint>

// SplitContextCenterConv2D as implicit GEMM on warp-level fp16 mma.sync.
// GEMM: M = 8*256*256 pixels, N = 256, K = 1152.
// CTA tile 128x256 (full N), 64x64 warp tiles, 1 CTA/SM.
// This round: A halo tile DOUBLE-buffered (refill overlaps compute, no
// serialized boundary), B weights in a 4-stage ring with prefetch distance 3
// (wait_group 3 never blocks). SMEM ~196KB/CTA.

#define HH 256
#define WW 256
#define CIN 128
#define COUT 256
#define KTOT 1152

#define ROWB 96                         // bytes per smem row (64B data + pad)
#define AROWS 518                       // 3*130 ctx halo rows + 128 center
#define A_BYTES (AROWS * ROWB)          // 49728
#define B_OFF (2 * A_BYTES)             // 99456
#define B_STAGE (256 * ROWB)            // 24576
#define SMEM_BYTES (B_OFF + 4 * B_STAGE)   // 197760

__device__ __half g_wt16[COUT * KTOT];  // fp16 weights, layout [n][k]

__global__ void wt_transform(const float* __restrict__ kern) {
    int o = blockIdx.x * 256 + threadIdx.x;
    if (o >= COUT * KTOT) return;
    int n = o / KTOT;
    int k = o - n * KTOT;
    int t = k >> 7;
    int ci = k & 127;
    int io = (t == 4) ? 1 : 0;
    float v = kern[(size_t)((t * 2 + io) * CIN + ci) * COUT + n];
    g_wt16[o] = __float2half_rn(v);
}

static __device__ __forceinline__ void cp16(uint32_t dst, const void* src) {
    asm volatile("cp.async.cg.shared.global [%0], [%1], 16;"
                 :: "r"(dst), "l"(src) : "memory");
}
static __device__ __forceinline__ uint32_t pack_h2(float lo, float hi) {
    uint32_t r;
    asm("cvt.rn.f16x2.f32 %0, %1, %2;" : "=r"(r) : "f"(hi), "f"(lo));
    return r;
}

__global__ __launch_bounds__(256, 1)
void conv_mma(const float* __restrict__ x, const float* __restrict__ bias,
              float* __restrict__ out) {
    extern __shared__ char smem[];
    const uint32_t smem_b = (uint32_t)__cvta_generic_to_shared(smem);

    const int tid  = threadIdx.x;
    const int wid  = tid >> 5;
    const int lane = tid & 31;
    const int g    = lane >> 2;   // 0..7
    const int tig  = lane & 3;    // 0..3

    const int m0 = (wid & 1) * 64;   // warp M offset (2 warps over M=128)
    const int n0 = (wid >> 1) * 64;  // warp N offset (4 warps over N=256)

    const int b  = blockIdx.z;
    const int h  = blockIdx.y;
    const int w0 = blockIdx.x * 128;
    const size_t img = (size_t)b * HH * WW * COUT;
    const float* xb = x + img;

    // ---------------- producer A invariants: 9 segment slots ----------------
    uint32_t aDst[9], aSrc[9];
    bool aOk[9];
#pragma unroll
    for (int s = 0; s < 7; s++) {
        int e = tid + 256 * s;
        int row = e >> 2, seg = e & 3;
        int rb = row / 130;
        int px = row - rb * 130;
        int gh = h - 1 + rb;
        int gw = w0 - 1 + px;
        bool ok = (e < 1560) && ((unsigned)gh < (unsigned)HH) &&
                  ((unsigned)gw < (unsigned)WW);
        aDst[s] = (uint32_t)(row * ROWB + seg * 16);
        aSrc[s] = ok ? (uint32_t)((gh * WW + gw) * COUT + seg * 8) : 0u;
        aOk[s] = ok;
    }
#pragma unroll
    for (int s = 7; s < 9; s++) {
        int row = (tid >> 2) + 64 * (s - 7);
        int seg = tid & 3;
        aDst[s] = (uint32_t)((390 + row) * ROWB + seg * 16);
        aSrc[s] = (uint32_t)((h * WW + w0 + row) * COUT + CIN + seg * 8);
        aOk[s] = true;
    }
    const bool sv6 = (tid < 24);

    // writes ci-chunk cc's halo tile into A buffer (cc&1)
    auto prodA = [&](int cc) {
        const uint32_t abuf = smem_b + (uint32_t)((cc & 1) * A_BYTES);
#pragma unroll
        for (int s = 0; s < 9; s++) {
            if (s == 6 && !sv6) continue;
            float4 v0 = make_float4(0.f, 0.f, 0.f, 0.f);
            float4 v1 = v0;
            if (aOk[s]) {
                const float* p = xb + aSrc[s] + cc * 32;
                v0 = *(const float4*)p;
                v1 = *(const float4*)(p + 4);
            }
            uint32_t h0 = pack_h2(v0.x, v0.y), h1 = pack_h2(v0.z, v0.w);
            uint32_t h2 = pack_h2(v1.x, v1.y), h3 = pack_h2(v1.z, v1.w);
            asm volatile("st.shared.v4.b32 [%0], {%1,%2,%3,%4};"
                         :: "r"(abuf + aDst[s]),
                            "r"(h0), "r"(h1), "r"(h2), "r"(h3) : "memory");
        }
    };

    // ---------------- B invariants: 256 rows x 4 segs = 4 per thread ----------
    const int bRow0 = tid >> 2, bSeg = tid & 3;
    uint32_t sdB[4], bOff[4];
#pragma unroll
    for (int i = 0; i < 4; i++) {
        int row = bRow0 + 64 * i;
        sdB[i] = (uint32_t)(B_OFF + row * ROWB + bSeg * 16);
        bOff[i] = (uint32_t)(row * KTOT + bSeg * 8);
    }
    auto cpB = [&](int ic) {           // ic compile-time after unroll
        int cc2 = ic / 9, t2 = ic - cc2 * 9;
        uint32_t st = smem_b + (uint32_t)((ic & 3) * B_STAGE);
        const __half* wb = g_wt16 + t2 * 128 + cc2 * 32;
#pragma unroll
        for (int i = 0; i < 4; i++)
            cp16(st + sdB[i], wb + bOff[i]);
        asm volatile("cp.async.commit_group;" ::: "memory");
    };

    // ---------------- fragment invariants ----------------
    uint32_t fA[4], fB[8];
#pragma unroll
    for (int mi = 0; mi < 4; mi++)
        fA[mi] = (uint32_t)((m0 + mi * 16 + g) * ROWB + tig * 8);
#pragma unroll
    for (int ni = 0; ni < 8; ni++)
        fB[ni] = (uint32_t)(B_OFF + (n0 + ni * 8 + g) * ROWB + tig * 8);

    float acc[4][8][4];
#pragma unroll
    for (int mi = 0; mi < 4; mi++)
#pragma unroll
        for (int ni = 0; ni < 8; ni++)
#pragma unroll
            for (int r = 0; r < 4; r++) acc[mi][ni][r] = 0.f;

    // ---------------- prologue: A tile 0 + B stages 0..2 ----------------
    prodA(0);
    cpB(0); cpB(1); cpB(2);
    asm volatile("cp.async.wait_group 2;" ::: "memory");
    __syncthreads();

    // ---------------- main: 4 ci-chunks x 9 taps ----------------
#pragma unroll
    for (int cc = 0; cc < 4; cc++) {
        const uint32_t aBuf = (uint32_t)((cc & 1) * A_BYTES);
#pragma unroll
        for (int t = 0; t < 9; t++) {
            const int ic = cc * 9 + t;
            if (ic + 3 < 36) cpB(ic + 3);

            const uint32_t tapOff = aBuf + ((t == 4)
                ? (uint32_t)(390 * ROWB)
                : (uint32_t)(((t / 3) * 130 + (t % 3)) * ROWB));
            const uint32_t bSt = (uint32_t)((ic & 3) * B_STAGE);

            // k-slot pairing: smem pos 4q,4q+1 -> MMA slots 2q,2q+1;
            // 4q+2,4q+3 -> 2q+8,2q+9, identical on A and B.
#pragma unroll
            for (int ks = 0; ks < 2; ks++) {
                uint32_t aF[4][4];
#pragma unroll
                for (int mi = 0; mi < 4; mi++) {
                    asm volatile("ld.shared.v2.b32 {%0, %1}, [%2];"
                                 : "=r"(aF[mi][0]), "=r"(aF[mi][2])
                                 : "r"(smem_b + fA[mi] + tapOff + ks * 32));
                    asm volatile("ld.shared.v2.b32 {%0, %1}, [%2];"
                                 : "=r"(aF[mi][1]), "=r"(aF[mi][3])
                                 : "r"(smem_b + fA[mi] + tapOff + 8 * ROWB + ks * 32));
                }
                uint32_t bF[8][2];
#pragma unroll
                for (int ni = 0; ni < 8; ni++)
                    asm volatile("ld.shared.v2.b32 {%0, %1}, [%2];"
                                 : "=r"(bF[ni][0]), "=r"(bF[ni][1])
                                 : "r"(smem_b + fB[ni] + bSt + ks * 32));
#pragma unroll
                for (int mi = 0; mi < 4; mi++)
#pragma unroll
                    for (int ni = 0; ni < 8; ni++)
                        asm volatile(
                            "mma.sync.aligned.m16n8k16.row.col.f32.f16.f16.f32 "
                            "{%0,%1,%2,%3}, {%4,%5,%6,%7}, {%8,%9}, {%0,%1,%2,%3};"
                            : "+f"(acc[mi][ni][0]), "+f"(acc[mi][ni][1]),
                              "+f"(acc[mi][ni][2]), "+f"(acc[mi][ni][3])
                            : "r"(aF[mi][0]), "r"(aF[mi][1]),
                              "r"(aF[mi][2]), "r"(aF[mi][3]),
                              "r"(bF[ni][0]), "r"(bF[ni][1]));
            }

            // mid-chunk: refill the OTHER A buffer for the next ci-chunk;
            // LDG latency hides under taps 5..8's MMA work. Visibility for
            // next chunk's readers comes from the per-chunk barrier below.
            if (t == 4 && cc < 3) prodA(cc + 1);

            // B stage ic was issued 3 chunks ago -> this wait never blocks.
            asm volatile("cp.async.wait_group 3;" ::: "memory");
            __syncthreads();
        }
    }

    // ---------------- epilogue ----------------
    float bv[8][2];
#pragma unroll
    for (int ni = 0; ni < 8; ni++) {
        int n = n0 + ni * 8 + tig * 2;
        bv[ni][0] = bias[n];
        bv[ni][1] = bias[n + 1];
    }
#pragma unroll
    for (int mi = 0; mi < 4; mi++) {
        int r0 = m0 + mi * 16 + g;
        float* p0 = out + img + ((size_t)h * WW + (w0 + r0)) * COUT;
        float* p1 = out + img + ((size_t)h * WW + (w0 + r0 + 8)) * COUT;
#pragma unroll
        for (int ni = 0; ni < 8; ni++) {
            int n = n0 + ni * 8 + tig * 2;
            float2 v0 = make_float2(acc[mi][ni][0] + bv[ni][0],
                                    acc[mi][ni][1] + bv[ni][1]);
            float2 v1 = make_float2(acc[mi][ni][2] + bv[ni][0],
                                    acc[mi][ni][3] + bv[ni][1]);
            *(float2*)(p0 + n) = v0;
            *(float2*)(p1 + n) = v1;
        }
    }
}

extern "C" void kernel_launch(void* const* d_in, const int* in_sizes, int n_in,
                              void* d_out, int out_size) {
    (void)in_sizes; (void)n_in; (void)out_size;
    const float* x    = (const float*)d_in[0];
    const float* kern = (const float*)d_in[1];
    const float* bias = (const float*)d_in[2];
    float* out = (float*)d_out;

    wt_transform<<<(COUT * KTOT + 255) / 256, 256>>>(kern);

    cudaFuncSetAttribute(conv_mma, cudaFuncAttributeMaxDynamicSharedMemorySize, SMEM_BYTES);
    dim3 grid(WW / 128, HH, 8);   // (2, 256, 8) = 4096 CTAs, full N per CTA
    conv_mma<<<grid, 256, SMEM_BYTES>>>(x, bias, out);
}